// round 2
// baseline (speedup 1.0000x reference)
#include <cuda_runtime.h>
#include <cuda_bf16.h>
#include <math.h>
#include <stdint.h>

#define NNODES 100000
#define NEDGES 1600000
#define FDIN   256
#define FH     256
#define FOUT   64

// ---------------- scratch (device globals; no runtime allocation) ----------------
__device__ float g_buf0[(size_t)NNODES * 256];
__device__ float g_buf1[(size_t)NNODES * 256];
__device__ float g_buf2[(size_t)NNODES * 256];
__device__ float g_buf3[(size_t)NNODES * 256];

__device__ int   g_rowptrA[NNODES + 1];
__device__ int   g_colA[NEDGES];
__device__ float g_valA[NEDGES];
__device__ int   g_rowptrL[NNODES + 1];
__device__ int   g_colL[NEDGES];
__device__ float g_valL[NEDGES];
__device__ int   g_cnt[NNODES];
__device__ int   g_cur[NNODES];
__device__ int   g_part[256];
__device__ int   g_partex[256];

// ---------------- CSR build ----------------
__global__ void k_zero_int(int* p, int n) {
    int i = blockIdx.x * blockDim.x + threadIdx.x;
    if (i < n) p[i] = 0;
}

__global__ void k_count(const int* __restrict__ rows, int* __restrict__ cnt, int E) {
    int e = blockIdx.x * blockDim.x + threadIdx.x;
    if (e < E) atomicAdd(&cnt[rows[e]], 1);
}

// ---- 3-phase scan: chunk = 1024 elements per block ----
__global__ void k_scan_reduce(const int* __restrict__ cnt, int* __restrict__ part, int n) {
    int chunk = blockIdx.x;
    int tid = threadIdx.x;                 // 256 threads
    int base = chunk * 1024;
    int s = 0;
    for (int i = tid; i < 1024; i += 256) {
        int idx = base + i;
        if (idx < n) s += cnt[idx];
    }
#pragma unroll
    for (int off = 16; off > 0; off >>= 1) s += __shfl_down_sync(0xffffffffu, s, off);
    __shared__ int ws[8];
    if ((tid & 31) == 0) ws[tid >> 5] = s;
    __syncthreads();
    if (tid < 8) {
        int v = ws[tid];
#pragma unroll
        for (int off = 4; off > 0; off >>= 1) v += __shfl_down_sync(0xffu, v, off);
        if (tid == 0) part[chunk] = v;
    }
}

__global__ void k_scan_part(const int* __restrict__ part, int* __restrict__ partex, int np) {
    __shared__ int sh[128];
    int tid = threadIdx.x;                 // 128 threads, np <= 128
    int v = (tid < np) ? part[tid] : 0;
    sh[tid] = v;
    __syncthreads();
    for (int off = 1; off < 128; off <<= 1) {
        int t = (tid >= off) ? sh[tid - off] : 0;
        __syncthreads();
        sh[tid] += t;
        __syncthreads();
    }
    if (tid < np) partex[tid] = sh[tid] - v;  // exclusive
}

__global__ void k_scan_final(const int* __restrict__ cnt, const int* __restrict__ partex,
                             int* __restrict__ rowptr, int n) {
    __shared__ int sh[256];
    int chunk = blockIdx.x;
    int tid = threadIdx.x;                 // 256 threads, 4 elems each
    int base = chunk * 1024;
    int v[4];
    int s = 0;
#pragma unroll
    for (int i = 0; i < 4; i++) {
        int idx = base + tid * 4 + i;
        v[i] = (idx < n) ? cnt[idx] : 0;
        s += v[i];
    }
    sh[tid] = s;
    __syncthreads();
    for (int off = 1; off < 256; off <<= 1) {
        int t = (tid >= off) ? sh[tid - off] : 0;
        __syncthreads();
        sh[tid] += t;
        __syncthreads();
    }
    int run = (tid ? sh[tid - 1] : 0) + partex[chunk];
#pragma unroll
    for (int i = 0; i < 4; i++) {
        run += v[i];
        int idx = base + tid * 4 + i;
        if (idx < n) rowptr[idx + 1] = run;
    }
    if (chunk == 0 && tid == 0) rowptr[0] = 0;
}

__global__ void k_scatter(const int* __restrict__ rows, const int* __restrict__ cols,
                          const float* __restrict__ vals,
                          const int* __restrict__ rowptr, int* __restrict__ cur,
                          int* __restrict__ colO, float* __restrict__ valO, int E) {
    int e = blockIdx.x * blockDim.x + threadIdx.x;
    if (e >= E) return;
    int r = rows[e];
    int p = rowptr[r] + atomicAdd(&cur[r], 1);
    colO[p] = cols[e];
    valO[p] = vals[e];
}

// ---------------- activations ----------------
__device__ __forceinline__ float actf(float x) {
    float s1 = fmaxf(x - 0.1f, 0.f) - fmaxf(-x - 0.1f, 0.f);
    float s2 = fmaxf(x - 0.5f, 0.f) - fmaxf(-x - 0.5f, 0.f);
    return 1.8f * s1 - 0.8f * s2;
}

// ---------------- CSR SpMM (row-parallel, float4 lanes) ----------------
template <int F4>
__global__ void k_spmm_relu(const int* __restrict__ rowptr, const int* __restrict__ col,
                            const float* __restrict__ val, const float* __restrict__ X,
                            const float* __restrict__ bias, float* __restrict__ out) {
    int t = blockIdx.x * blockDim.x + threadIdx.x;
    int row = t / F4;
    int f = t % F4;
    if (row >= NNODES) return;
    int s = rowptr[row], e = rowptr[row + 1];
    const float4* X4 = (const float4*)X;
    float4 acc = make_float4(0.f, 0.f, 0.f, 0.f);
    for (int p = s; p < e; p++) {
        int c = __ldg(&col[p]);
        float v = __ldg(&val[p]);
        float4 xv = X4[(size_t)c * F4 + f];
        acc.x = fmaf(v, xv.x, acc.x);
        acc.y = fmaf(v, xv.y, acc.y);
        acc.z = fmaf(v, xv.z, acc.z);
        acc.w = fmaf(v, xv.w, acc.w);
    }
    float4 b = ((const float4*)bias)[f];
    float4 o;
    o.x = fmaxf(acc.x + b.x, 0.f);
    o.y = fmaxf(acc.y + b.y, 0.f);
    o.z = fmaxf(acc.z + b.z, 0.f);
    o.w = fmaxf(acc.w + b.w, 0.f);
    ((float4*)out)[(size_t)row * F4 + f] = o;
}

template <int F4>
__global__ void k_spmm_embed(const int* __restrict__ rowptr, const int* __restrict__ col,
                             const float* __restrict__ val, const float* __restrict__ X,
                             const float* __restrict__ T, float* __restrict__ out) {
    int t = blockIdx.x * blockDim.x + threadIdx.x;
    int row = t / F4;
    int f = t % F4;
    if (row >= NNODES) return;
    int s = rowptr[row], e = rowptr[row + 1];
    const float4* X4 = (const float4*)X;
    float4 acc = make_float4(0.f, 0.f, 0.f, 0.f);
    for (int p = s; p < e; p++) {
        int c = __ldg(&col[p]);
        float v = __ldg(&val[p]);
        float4 xv = X4[(size_t)c * F4 + f];
        acc.x = fmaf(v, xv.x, acc.x);
        acc.y = fmaf(v, xv.y, acc.y);
        acc.z = fmaf(v, xv.z, acc.z);
        acc.w = fmaf(v, xv.w, acc.w);
    }
    float4 tv = ((const float4*)T)[(size_t)row * F4 + f];
    float4 o;
    o.x = actf(tv.x - acc.x);
    o.y = actf(tv.y - acc.y);
    o.z = actf(tv.z - acc.z);
    o.w = actf(tv.w - acc.w);
    ((float4*)out)[(size_t)row * F4 + f] = o;
}

// ---------------- tensor-core GEMM (bf16x3 split, fp32 accuracy) ----------------
// C[M,Nc] = concat_K(A1[M,K1], A2[M,K2]) @ concat_K(B1, B2)  (+bias) (tanh if actFlag)
// BM=128, BN=64, BK=32. 256 threads = 8 warps (4 along M x 2 along N), warp tile 32x32.
#define GBM 128
#define GBN 64
#define GBK 32
#define GSTR 40   // bf16 row stride with pad

__device__ __forceinline__ void mma_bf16(float& d0, float& d1, float& d2, float& d3,
                                         uint32_t a0, uint32_t a1, uint32_t a2, uint32_t a3,
                                         uint32_t b0, uint32_t b1) {
    asm volatile(
        "mma.sync.aligned.m16n8k16.row.col.f32.bf16.bf16.f32 "
        "{%0,%1,%2,%3}, {%4,%5,%6,%7}, {%8,%9}, {%0,%1,%2,%3};"
        : "+f"(d0), "+f"(d1), "+f"(d2), "+f"(d3)
        : "r"(a0), "r"(a1), "r"(a2), "r"(a3), "r"(b0), "r"(b1));
}

__global__ __launch_bounds__(256) void k_gemm_tc(
    const float* __restrict__ A1, int K1, const float* __restrict__ B1,
    const float* __restrict__ A2, int K2, const float* __restrict__ B2,
    float* __restrict__ C, int M, int Nc,
    const float* __restrict__ bias, int actFlag)
{
    __shared__ __nv_bfloat16 Ahi[GBM][GSTR];
    __shared__ __nv_bfloat16 Alo[GBM][GSTR];
    __shared__ __nv_bfloat16 Bhi[GBN][GSTR];
    __shared__ __nv_bfloat16 Blo[GBN][GSTR];

    int tid = threadIdx.x;
    int warp = tid >> 5, lane = tid & 31;
    int wm = warp & 3;    // warp row block (32 rows)
    int wn = warp >> 2;   // warp col block (32 cols)
    int bm = blockIdx.x * GBM, bn = blockIdx.y * GBN;

    float acc[2][4][4];
#pragma unroll
    for (int i = 0; i < 2; i++)
#pragma unroll
        for (int j = 0; j < 4; j++)
#pragma unroll
            for (int c = 0; c < 4; c++) acc[i][j][c] = 0.f;

    int Ktot = K1 + K2;
    for (int k0 = 0; k0 < Ktot; k0 += GBK) {
        const float* A;
        const float* B;
        int kloc, Kcur;
        if (k0 < K1) { A = A1; B = B1; kloc = k0; Kcur = K1; }
        else         { A = A2; B = B2; kloc = k0 - K1; Kcur = K2; }

        // load + split A tile: 128 x 32 floats (4 float4 per thread)
#pragma unroll
        for (int r = 0; r < 4; r++) {
            int idx = tid * 4 + r;
            int row = idx >> 3;        // 8 float4 per 32-col row
            int c4 = idx & 7;
            float4 v = make_float4(0.f, 0.f, 0.f, 0.f);
            int grow = bm + row;
            if (grow < M) v = *(const float4*)(A + (size_t)grow * Kcur + kloc + c4 * 4);
            float vv[4] = {v.x, v.y, v.z, v.w};
#pragma unroll
            for (int j = 0; j < 4; j++) {
                __nv_bfloat16 h = __float2bfloat16(vv[j]);
                Ahi[row][c4 * 4 + j] = h;
                Alo[row][c4 * 4 + j] = __float2bfloat16(vv[j] - __bfloat162float(h));
            }
        }
        // load + split B tile: 32 x 64 floats (2 float4 per thread), transposed -> Bs[n][k]
#pragma unroll
        for (int r = 0; r < 2; r++) {
            int idx = tid * 2 + r;
            int krow = idx >> 4;       // 16 float4 per 64-col row
            int c4 = idx & 15;
            float4 v = *(const float4*)(B + (size_t)(kloc + krow) * Nc + bn + c4 * 4);
            float vv[4] = {v.x, v.y, v.z, v.w};
#pragma unroll
            for (int j = 0; j < 4; j++) {
                __nv_bfloat16 h = __float2bfloat16(vv[j]);
                Bhi[c4 * 4 + j][krow] = h;
                Blo[c4 * 4 + j][krow] = __float2bfloat16(vv[j] - __bfloat162float(h));
            }
        }
        __syncthreads();

#pragma unroll
        for (int ks = 0; ks < GBK; ks += 16) {
            int c = ks + (lane & 3) * 2;
            uint32_t ahi[2][4], alo[2][4], bhi[4][2], blo[4][2];
#pragma unroll
            for (int mf = 0; mf < 2; mf++) {
                int r = wm * 32 + mf * 16 + (lane >> 2);
                ahi[mf][0] = *(const uint32_t*)&Ahi[r][c];
                ahi[mf][1] = *(const uint32_t*)&Ahi[r + 8][c];
                ahi[mf][2] = *(const uint32_t*)&Ahi[r][c + 8];
                ahi[mf][3] = *(const uint32_t*)&Ahi[r + 8][c + 8];
                alo[mf][0] = *(const uint32_t*)&Alo[r][c];
                alo[mf][1] = *(const uint32_t*)&Alo[r + 8][c];
                alo[mf][2] = *(const uint32_t*)&Alo[r][c + 8];
                alo[mf][3] = *(const uint32_t*)&Alo[r + 8][c + 8];
            }
#pragma unroll
            for (int nf = 0; nf < 4; nf++) {
                int n = wn * 32 + nf * 8 + (lane >> 2);
                bhi[nf][0] = *(const uint32_t*)&Bhi[n][c];
                bhi[nf][1] = *(const uint32_t*)&Bhi[n][c + 8];
                blo[nf][0] = *(const uint32_t*)&Blo[n][c];
                blo[nf][1] = *(const uint32_t*)&Blo[n][c + 8];
            }
#pragma unroll
            for (int mf = 0; mf < 2; mf++)
#pragma unroll
                for (int nf = 0; nf < 4; nf++) {
                    float* d = acc[mf][nf];
                    mma_bf16(d[0], d[1], d[2], d[3],
                             ahi[mf][0], ahi[mf][1], ahi[mf][2], ahi[mf][3],
                             bhi[nf][0], bhi[nf][1]);
                    mma_bf16(d[0], d[1], d[2], d[3],
                             ahi[mf][0], ahi[mf][1], ahi[mf][2], ahi[mf][3],
                             blo[nf][0], blo[nf][1]);
                    mma_bf16(d[0], d[1], d[2], d[3],
                             alo[mf][0], alo[mf][1], alo[mf][2], alo[mf][3],
                             bhi[nf][0], bhi[nf][1]);
                }
        }
        __syncthreads();
    }

    // epilogue
#pragma unroll
    for (int mf = 0; mf < 2; mf++) {
        int row0 = bm + wm * 32 + mf * 16 + (lane >> 2);
#pragma unroll
        for (int nf = 0; nf < 4; nf++) {
            int col = bn + wn * 32 + nf * 8 + (lane & 3) * 2;
            float b0 = bias ? bias[col] : 0.f;
            float b1 = bias ? bias[col + 1] : 0.f;
            float* d = acc[mf][nf];
            float c0 = d[0] + b0, c1 = d[1] + b1, c2 = d[2] + b0, c3 = d[3] + b1;
            if (actFlag) { c0 = tanhf(c0); c1 = tanhf(c1); c2 = tanhf(c2); c3 = tanhf(c3); }
            if (row0 < M) *(float2*)(C + (size_t)row0 * Nc + col) = make_float2(c0, c1);
            if (row0 + 8 < M) *(float2*)(C + (size_t)(row0 + 8) * Nc + col) = make_float2(c2, c3);
        }
    }
}

// ---------------- host orchestration ----------------
static inline void gemm2(const float* A1, int K1, const float* B1,
                         const float* A2, int K2, const float* B2,
                         float* C, int M, int Nc, const float* bias, int actFlag) {
    dim3 grid((M + GBM - 1) / GBM, Nc / GBN);
    k_gemm_tc<<<grid, 256>>>(A1, K1, B1, A2, K2, B2, C, M, Nc, bias, actFlag);
}
static inline void gemm1(const float* A, int K, const float* B,
                         float* C, int M, int Nc, const float* bias, int actFlag) {
    gemm2(A, K, B, nullptr, 0, nullptr, C, M, Nc, bias, actFlag);
}

extern "C" void kernel_launch(void* const* d_in, const int* in_sizes, int n_in,
                              void* d_out, int out_size) {
    (void)in_sizes; (void)n_in; (void)out_size;
    const float* x      = (const float*)d_in[0];
    const int*   A_idx  = (const int*)d_in[1];
    const float* A_val  = (const float*)d_in[2];
    const int*   L_idx  = (const int*)d_in[3];
    const float* L_val  = (const float*)d_in[4];
    const float* gcn_w0 = (const float*)d_in[5];
    const float* gcn_b0 = (const float*)d_in[6];
    const float* pai1_0 = (const float*)d_in[7];
    const float* pai2_0 = (const float*)d_in[8];
    const float* w1_w0  = (const float*)d_in[9];
    const float* w1_b0  = (const float*)d_in[10];
    const float* w2_w0  = (const float*)d_in[11];
    const float* w2_b0  = (const float*)d_in[12];
    const float* gcn_w1 = (const float*)d_in[13];
    const float* gcn_b1 = (const float*)d_in[14];
    const float* pai1_1 = (const float*)d_in[15];
    const float* pai2_1 = (const float*)d_in[16];
    const float* w1_w1  = (const float*)d_in[17];
    const float* w1_b1  = (const float*)d_in[18];
    const float* w2_w1  = (const float*)d_in[19];
    const float* w2_b1  = (const float*)d_in[20];

    float* out = (float*)d_out;
    float* out_ztp0 = out;
    float* out_ztp1 = out + (size_t)NNODES * FOUT;
    float* out_zem0 = out + (size_t)2 * NNODES * FOUT;
    float* out_zem1 = out + (size_t)3 * NNODES * FOUT;

    float *buf0, *buf1, *buf2, *buf3, *valA, *valL;
    int *rowptrA, *colA, *rowptrL, *colL, *cnt, *cur, *part, *partex;
    cudaGetSymbolAddress((void**)&buf0, g_buf0);
    cudaGetSymbolAddress((void**)&buf1, g_buf1);
    cudaGetSymbolAddress((void**)&buf2, g_buf2);
    cudaGetSymbolAddress((void**)&buf3, g_buf3);
    cudaGetSymbolAddress((void**)&rowptrA, g_rowptrA);
    cudaGetSymbolAddress((void**)&colA, g_colA);
    cudaGetSymbolAddress((void**)&valA, g_valA);
    cudaGetSymbolAddress((void**)&rowptrL, g_rowptrL);
    cudaGetSymbolAddress((void**)&colL, g_colL);
    cudaGetSymbolAddress((void**)&valL, g_valL);
    cudaGetSymbolAddress((void**)&cnt, g_cnt);
    cudaGetSymbolAddress((void**)&cur, g_cur);
    cudaGetSymbolAddress((void**)&part, g_part);
    cudaGetSymbolAddress((void**)&partex, g_partex);

    const int TB = 256;
    int gbN = (NNODES + TB - 1) / TB;
    int gbE = (NEDGES + TB - 1) / TB;
    int nChunks = (NNODES + 1023) / 1024;

    // ---- build CSR for A ----
    k_zero_int<<<gbN, TB>>>(cnt, NNODES);
    k_zero_int<<<gbN, TB>>>(cur, NNODES);
    k_count<<<gbE, TB>>>(A_idx, cnt, NEDGES);
    k_scan_reduce<<<nChunks, 256>>>(cnt, part, NNODES);
    k_scan_part<<<1, 128>>>(part, partex, nChunks);
    k_scan_final<<<nChunks, 256>>>(cnt, partex, rowptrA, NNODES);
    k_scatter<<<gbE, TB>>>(A_idx, A_idx + NEDGES, A_val, rowptrA, cur, colA, valA, NEDGES);
    // ---- build CSR for L ----
    k_zero_int<<<gbN, TB>>>(cnt, NNODES);
    k_zero_int<<<gbN, TB>>>(cur, NNODES);
    k_count<<<gbE, TB>>>(L_idx, cnt, NEDGES);
    k_scan_reduce<<<nChunks, 256>>>(cnt, part, NNODES);
    k_scan_part<<<1, 128>>>(part, partex, nChunks);
    k_scan_final<<<nChunks, 256>>>(cnt, partex, rowptrL, NNODES);
    k_scatter<<<gbE, TB>>>(L_idx, L_idx + NEDGES, L_val, rowptrL, cur, colL, valL, NEDGES);

    // ================= layer 0 (din=256 -> h=256) =================
    gemm1(x, FDIN, gcn_w0, buf0, NNODES, FH, nullptr, 0);
    {
        int threads = NNODES * (FH / 4);
        k_spmm_relu<FH / 4><<<(threads + TB - 1) / TB, TB>>>(rowptrA, colA, valA, buf0, gcn_b0, buf1);
    }
    gemm1(buf1, FH, w1_w0, out_ztp0, NNODES, FOUT, w1_b0, 1);
    gemm2(buf1, FH, pai1_0, x, FDIN, pai2_0, buf2, NNODES, FH, nullptr, 0);
    {
        int threads = NNODES * (FH / 4);
        k_spmm_embed<FH / 4><<<(threads + TB - 1) / TB, TB>>>(rowptrL, colL, valL, buf1, buf2, buf3);
    }
    gemm1(buf3, FH, w2_w0, out_zem0, NNODES, FOUT, w2_b0, 1);

    // ================= layer 1 (h=256 -> dout=64) =================
    gemm1(buf3, FH, gcn_w1, buf0, NNODES, FOUT, nullptr, 0);
    {
        int threads = NNODES * (FOUT / 4);
        k_spmm_relu<FOUT / 4><<<(threads + TB - 1) / TB, TB>>>(rowptrA, colA, valA, buf0, gcn_b1, buf1);
    }
    gemm1(buf1, FOUT, w1_w1, out_ztp1, NNODES, FOUT, w1_b1, 1);
    gemm2(buf1, FOUT, pai1_1, x, FDIN, pai2_1, buf2, NNODES, FOUT, nullptr, 0);
    {
        int threads = NNODES * (FOUT / 4);
        k_spmm_embed<FOUT / 4><<<(threads + TB - 1) / TB, TB>>>(rowptrL, colL, valL, buf1, buf2, buf3);
    }
    gemm1(buf3, FOUT, w2_w1, out_zem1, NNODES, FOUT, w2_b1, 1);
}

// round 3
// speedup vs baseline: 2.6334x; 2.6334x over previous
#include <cuda_runtime.h>
#include <cuda_bf16.h>
#include <math.h>
#include <stdint.h>

#define NNODES 100000
#define NEDGES 1600000
#define FDIN   256
#define FH     256
#define FOUT   64

typedef __nv_bfloat16 bf16;

// ---------------- scratch (device globals; no runtime allocation) ----------------
__device__ float g_buf0[(size_t)NNODES * 256];
__device__ float g_buf1[(size_t)NNODES * 256];
__device__ float g_buf2[(size_t)NNODES * 256];
__device__ float g_buf3[(size_t)NNODES * 256];

__device__ bf16 g_xhi[(size_t)NNODES * 256];
__device__ bf16 g_xlo[(size_t)NNODES * 256];
__device__ bf16 g_zhi[(size_t)NNODES * 256];
__device__ bf16 g_zlo[(size_t)NNODES * 256];
__device__ bf16 g_whi[300000];
__device__ bf16 g_wlo[300000];

__device__ int   g_rowptrA[NNODES + 1];
__device__ int   g_colA[NEDGES];
__device__ float g_valA[NEDGES];
__device__ int   g_rowptrL[NNODES + 1];
__device__ int   g_colL[NEDGES];
__device__ float g_valL[NEDGES];
__device__ int   g_cnt[NNODES];
__device__ int   g_cur[NNODES];
__device__ int   g_part[256];
__device__ int   g_partex[256];

// weight packing offsets
#define OFF_GCN_W0 0
#define OFF_PAI1_0 65536
#define OFF_PAI2_0 131072
#define OFF_W1_W0  196608
#define OFF_W2_W0  212992
#define OFF_GCN_W1 229376
#define OFF_PAI1_1 245760
#define OFF_PAI2_1 249856
#define OFF_W1_W1  266240
#define OFF_W2_W1  270336

// ---------------- CSR build ----------------
__global__ void k_zero_int(int* p, int n) {
    int i = blockIdx.x * blockDim.x + threadIdx.x;
    if (i < n) p[i] = 0;
}

__global__ void k_count(const int* __restrict__ rows, int* __restrict__ cnt, int E) {
    int e = blockIdx.x * blockDim.x + threadIdx.x;
    if (e < E) atomicAdd(&cnt[rows[e]], 1);
}

__global__ void k_scan_reduce(const int* __restrict__ cnt, int* __restrict__ part, int n) {
    int chunk = blockIdx.x;
    int tid = threadIdx.x;
    int base = chunk * 1024;
    int s = 0;
    for (int i = tid; i < 1024; i += 256) {
        int idx = base + i;
        if (idx < n) s += cnt[idx];
    }
#pragma unroll
    for (int off = 16; off > 0; off >>= 1) s += __shfl_down_sync(0xffffffffu, s, off);
    __shared__ int ws[8];
    if ((tid & 31) == 0) ws[tid >> 5] = s;
    __syncthreads();
    if (tid < 8) {
        int v = ws[tid];
#pragma unroll
        for (int off = 4; off > 0; off >>= 1) v += __shfl_down_sync(0xffu, v, off);
        if (tid == 0) part[chunk] = v;
    }
}

__global__ void k_scan_part(const int* __restrict__ part, int* __restrict__ partex, int np) {
    __shared__ int sh[128];
    int tid = threadIdx.x;
    int v = (tid < np) ? part[tid] : 0;
    sh[tid] = v;
    __syncthreads();
    for (int off = 1; off < 128; off <<= 1) {
        int t = (tid >= off) ? sh[tid - off] : 0;
        __syncthreads();
        sh[tid] += t;
        __syncthreads();
    }
    if (tid < np) partex[tid] = sh[tid] - v;
}

__global__ void k_scan_final(const int* __restrict__ cnt, const int* __restrict__ partex,
                             int* __restrict__ rowptr, int n) {
    __shared__ int sh[256];
    int chunk = blockIdx.x;
    int tid = threadIdx.x;
    int base = chunk * 1024;
    int v[4];
    int s = 0;
#pragma unroll
    for (int i = 0; i < 4; i++) {
        int idx = base + tid * 4 + i;
        v[i] = (idx < n) ? cnt[idx] : 0;
        s += v[i];
    }
    sh[tid] = s;
    __syncthreads();
    for (int off = 1; off < 256; off <<= 1) {
        int t = (tid >= off) ? sh[tid - off] : 0;
        __syncthreads();
        sh[tid] += t;
        __syncthreads();
    }
    int run = (tid ? sh[tid - 1] : 0) + partex[chunk];
#pragma unroll
    for (int i = 0; i < 4; i++) {
        run += v[i];
        int idx = base + tid * 4 + i;
        if (idx < n) rowptr[idx + 1] = run;
    }
    if (chunk == 0 && tid == 0) rowptr[0] = 0;
}

__global__ void k_scatter(const int* __restrict__ rows, const int* __restrict__ cols,
                          const float* __restrict__ vals,
                          const int* __restrict__ rowptr, int* __restrict__ cur,
                          int* __restrict__ colO, float* __restrict__ valO, int E) {
    int e = blockIdx.x * blockDim.x + threadIdx.x;
    if (e >= E) return;
    int r = rows[e];
    int p = rowptr[r] + atomicAdd(&cur[r], 1);
    colO[p] = cols[e];
    valO[p] = vals[e];
}

// ---------------- fp32 -> bf16 hi/lo split ----------------
__global__ void k_split(const float* __restrict__ src, bf16* __restrict__ hi,
                        bf16* __restrict__ lo, int n4) {
    int i = blockIdx.x * blockDim.x + threadIdx.x;
    if (i >= n4) return;
    float4 v = ((const float4*)src)[i];
    __nv_bfloat162 h01 = __floats2bfloat162_rn(v.x, v.y);
    __nv_bfloat162 h23 = __floats2bfloat162_rn(v.z, v.w);
    float lx = v.x - __bfloat162float(h01.x);
    float ly = v.y - __bfloat162float(h01.y);
    float lz = v.z - __bfloat162float(h23.x);
    float lw = v.w - __bfloat162float(h23.y);
    __nv_bfloat162 l01 = __floats2bfloat162_rn(lx, ly);
    __nv_bfloat162 l23 = __floats2bfloat162_rn(lz, lw);
    ((__nv_bfloat162*)hi)[i * 2] = h01;
    ((__nv_bfloat162*)hi)[i * 2 + 1] = h23;
    ((__nv_bfloat162*)lo)[i * 2] = l01;
    ((__nv_bfloat162*)lo)[i * 2 + 1] = l23;
}

struct WSplit {
    const float* src[10];
    int n4[10];
    int off[10];
};

__global__ void k_split_weights(WSplit ws, bf16* __restrict__ hi, bf16* __restrict__ lo) {
    int t = blockIdx.y;
    int i = blockIdx.x * blockDim.x + threadIdx.x;
    if (i >= ws.n4[t]) return;
    float4 v = ((const float4*)ws.src[t])[i];
    __nv_bfloat162 h01 = __floats2bfloat162_rn(v.x, v.y);
    __nv_bfloat162 h23 = __floats2bfloat162_rn(v.z, v.w);
    float lx = v.x - __bfloat162float(h01.x);
    float ly = v.y - __bfloat162float(h01.y);
    float lz = v.z - __bfloat162float(h23.x);
    float lw = v.w - __bfloat162float(h23.y);
    __nv_bfloat162 l01 = __floats2bfloat162_rn(lx, ly);
    __nv_bfloat162 l23 = __floats2bfloat162_rn(lz, lw);
    __nv_bfloat162* hp = (__nv_bfloat162*)(hi + ws.off[t]);
    __nv_bfloat162* lp = (__nv_bfloat162*)(lo + ws.off[t]);
    hp[i * 2] = h01;
    hp[i * 2 + 1] = h23;
    lp[i * 2] = l01;
    lp[i * 2 + 1] = l23;
}

// ---------------- activations ----------------
__device__ __forceinline__ float actf(float x) {
    float s1 = fmaxf(x - 0.1f, 0.f) - fmaxf(-x - 0.1f, 0.f);
    float s2 = fmaxf(x - 0.5f, 0.f) - fmaxf(-x - 0.5f, 0.f);
    return 1.8f * s1 - 0.8f * s2;
}

// ---------------- CSR SpMM (row-parallel, float4 lanes) ----------------
template <int F4>
__global__ void k_spmm_relu(const int* __restrict__ rowptr, const int* __restrict__ col,
                            const float* __restrict__ val, const float* __restrict__ X,
                            const float* __restrict__ bias, float* __restrict__ out) {
    int t = blockIdx.x * blockDim.x + threadIdx.x;
    int row = t / F4;
    int f = t % F4;
    if (row >= NNODES) return;
    int s = rowptr[row], e = rowptr[row + 1];
    const float4* X4 = (const float4*)X;
    float4 acc = make_float4(0.f, 0.f, 0.f, 0.f);
    for (int p = s; p < e; p++) {
        int c = __ldg(&col[p]);
        float v = __ldg(&val[p]);
        float4 xv = X4[(size_t)c * F4 + f];
        acc.x = fmaf(v, xv.x, acc.x);
        acc.y = fmaf(v, xv.y, acc.y);
        acc.z = fmaf(v, xv.z, acc.z);
        acc.w = fmaf(v, xv.w, acc.w);
    }
    float4 b = ((const float4*)bias)[f];
    float4 o;
    o.x = fmaxf(acc.x + b.x, 0.f);
    o.y = fmaxf(acc.y + b.y, 0.f);
    o.z = fmaxf(acc.z + b.z, 0.f);
    o.w = fmaxf(acc.w + b.w, 0.f);
    ((float4*)out)[(size_t)row * F4 + f] = o;
}

template <int F4>
__global__ void k_spmm_embed(const int* __restrict__ rowptr, const int* __restrict__ col,
                             const float* __restrict__ val, const float* __restrict__ X,
                             const float* __restrict__ T, float* __restrict__ out) {
    int t = blockIdx.x * blockDim.x + threadIdx.x;
    int row = t / F4;
    int f = t % F4;
    if (row >= NNODES) return;
    int s = rowptr[row], e = rowptr[row + 1];
    const float4* X4 = (const float4*)X;
    float4 acc = make_float4(0.f, 0.f, 0.f, 0.f);
    for (int p = s; p < e; p++) {
        int c = __ldg(&col[p]);
        float v = __ldg(&val[p]);
        float4 xv = X4[(size_t)c * F4 + f];
        acc.x = fmaf(v, xv.x, acc.x);
        acc.y = fmaf(v, xv.y, acc.y);
        acc.z = fmaf(v, xv.z, acc.z);
        acc.w = fmaf(v, xv.w, acc.w);
    }
    float4 tv = ((const float4*)T)[(size_t)row * F4 + f];
    float4 o;
    o.x = actf(tv.x - acc.x);
    o.y = actf(tv.y - acc.y);
    o.z = actf(tv.z - acc.z);
    o.w = actf(tv.w - acc.w);
    ((float4*)out)[(size_t)row * F4 + f] = o;
}

// ---------------- tensor-core GEMM (pre-split bf16x3, cp.async + ldmatrix) ----------------
// BM=128, BN=64, BK=32, 256 threads = 8 warps (4 M x 2 N), warp tile 32x32.
// grid: (Nc/64, ceil(M/128)) -- N fastest for L2 reuse of A tiles.

__device__ __forceinline__ uint32_t s2u(const void* p) {
    return (uint32_t)__cvta_generic_to_shared(p);
}

// smem byte offsets with XOR swizzle (16B chunk granularity)
__device__ __forceinline__ int aoff(int row, int k) {
    // row stride 64B (32 bf16), chunk = k>>3
    return row * 64 + (((k >> 3) ^ ((row >> 1) & 3)) << 4) + ((k & 7) << 1);
}
__device__ __forceinline__ int boff(int kr, int n) {
    // row stride 128B (64 bf16), chunk = n>>3
    return kr * 128 + (((n >> 3) ^ (kr & 7)) << 4) + ((n & 7) << 1);
}

__device__ __forceinline__ void cp16(uint32_t dst, const void* src) {
    asm volatile("cp.async.cg.shared.global [%0], [%1], 16;\n" ::"r"(dst), "l"(src));
}
__device__ __forceinline__ void ldm_x4(uint32_t addr, uint32_t& r0, uint32_t& r1,
                                       uint32_t& r2, uint32_t& r3) {
    asm volatile("ldmatrix.sync.aligned.m8n8.x4.shared.b16 {%0,%1,%2,%3}, [%4];\n"
                 : "=r"(r0), "=r"(r1), "=r"(r2), "=r"(r3) : "r"(addr));
}
__device__ __forceinline__ void ldm_x4t(uint32_t addr, uint32_t& r0, uint32_t& r1,
                                        uint32_t& r2, uint32_t& r3) {
    asm volatile("ldmatrix.sync.aligned.m8n8.x4.trans.shared.b16 {%0,%1,%2,%3}, [%4];\n"
                 : "=r"(r0), "=r"(r1), "=r"(r2), "=r"(r3) : "r"(addr));
}
__device__ __forceinline__ void mma_bf16(float& d0, float& d1, float& d2, float& d3,
                                         uint32_t a0, uint32_t a1, uint32_t a2, uint32_t a3,
                                         uint32_t b0, uint32_t b1) {
    asm volatile(
        "mma.sync.aligned.m16n8k16.row.col.f32.bf16.bf16.f32 "
        "{%0,%1,%2,%3}, {%4,%5,%6,%7}, {%8,%9}, {%0,%1,%2,%3};"
        : "+f"(d0), "+f"(d1), "+f"(d2), "+f"(d3)
        : "r"(a0), "r"(a1), "r"(a2), "r"(a3), "r"(b0), "r"(b1));
}

__global__ __launch_bounds__(256) void k_gemm_tc(
    const bf16* __restrict__ A1hi, const bf16* __restrict__ A1lo, int K1,
    const bf16* __restrict__ B1hi, const bf16* __restrict__ B1lo,
    const bf16* __restrict__ A2hi, const bf16* __restrict__ A2lo, int K2,
    const bf16* __restrict__ B2hi, const bf16* __restrict__ B2lo,
    float* __restrict__ C, int M, int Nc,
    const float* __restrict__ bias, int actFlag)
{
    __shared__ __align__(16) bf16 sA[2][2][128 * 32];  // [stage][hi/lo] 8192B each
    __shared__ __align__(16) bf16 sB[2][2][32 * 64];   // [stage][hi/lo] 4096B each

    int tid = threadIdx.x;
    int warp = tid >> 5, lane = tid & 31;
    int wm = warp & 3;
    int wn = warp >> 2;
    int bn = blockIdx.x * 64;
    int bm = blockIdx.y * 128;

    float acc[2][4][4];
#pragma unroll
    for (int i = 0; i < 2; i++)
#pragma unroll
        for (int j = 0; j < 4; j++)
#pragma unroll
            for (int c = 0; c < 4; c++) acc[i][j][c] = 0.f;

    const int T = (K1 + K2) / 32;

    // per-thread load assignments
    // A: 512 chunks per matrix; thread handles chunks tid, tid+256
    // B: 256 chunks per matrix; thread handles chunk tid
    int arow0 = tid >> 2, ac0 = tid & 3;
    int arow1 = (tid + 256) >> 2, ac1 = tid & 3;  // (tid+256)&3 == tid&3
    int garow0 = bm + arow0; if (garow0 >= M) garow0 = M - 1;
    int garow1 = bm + arow1; if (garow1 >= M) garow1 = M - 1;
    int bkr = tid >> 3, bc = tid & 7;

    auto loadTile = [&](int t, int stage) {
        int k0 = t * 32;
        const bf16 *Ahi, *Alo, *Bhi, *Blo;
        int kloc, K;
        if (k0 < K1) { Ahi = A1hi; Alo = A1lo; Bhi = B1hi; Blo = B1lo; kloc = k0; K = K1; }
        else         { Ahi = A2hi; Alo = A2lo; Bhi = B2hi; Blo = B2lo; kloc = k0 - K1; K = K2; }
        uint32_t sa_hi = s2u(&sA[stage][0][0]);
        uint32_t sa_lo = s2u(&sA[stage][1][0]);
        uint32_t sb_hi = s2u(&sB[stage][0][0]);
        uint32_t sb_lo = s2u(&sB[stage][1][0]);
        int so0 = aoff(arow0, ac0 * 8);
        int so1 = aoff(arow1, ac1 * 8);
        size_t g0 = (size_t)garow0 * K + kloc + ac0 * 8;
        size_t g1 = (size_t)garow1 * K + kloc + ac1 * 8;
        cp16(sa_hi + so0, Ahi + g0);
        cp16(sa_hi + so1, Ahi + g1);
        cp16(sa_lo + so0, Alo + g0);
        cp16(sa_lo + so1, Alo + g1);
        int sob = boff(bkr, bc * 8);
        size_t gb = (size_t)(kloc + bkr) * Nc + bn + bc * 8;
        cp16(sb_hi + sob, Bhi + gb);
        cp16(sb_lo + sob, Blo + gb);
        asm volatile("cp.async.commit_group;\n");
    };

    loadTile(0, 0);

    // per-lane ldmatrix row/col pieces
    int a_r = (lane & 7) + ((lane & 8) ? 8 : 0);    // row within 16-row frag
    int a_k = (lane & 16) ? 8 : 0;                   // k offset within 16
    int b_k = (lane & 7) + ((lane & 8) ? 8 : 0);
    int b_n = (lane & 16) ? 8 : 0;

    for (int t = 0; t < T; t++) {
        int s = t & 1;
        if (t + 1 < T) {
            loadTile(t + 1, (t + 1) & 1);
            asm volatile("cp.async.wait_group 1;\n");
        } else {
            asm volatile("cp.async.wait_group 0;\n");
        }
        __syncthreads();

        uint32_t sa_hi = s2u(&sA[s][0][0]);
        uint32_t sa_lo = s2u(&sA[s][1][0]);
        uint32_t sb_hi = s2u(&sB[s][0][0]);
        uint32_t sb_lo = s2u(&sB[s][1][0]);

#pragma unroll
        for (int ks = 0; ks < 32; ks += 16) {
            uint32_t ahi[2][4], alo[2][4], bhi[4][2], blo[4][2];
#pragma unroll
            for (int mf = 0; mf < 2; mf++) {
                int row = wm * 32 + mf * 16 + a_r;
                int off = aoff(row, ks + a_k);
                ldm_x4(sa_hi + off, ahi[mf][0], ahi[mf][1], ahi[mf][2], ahi[mf][3]);
                ldm_x4(sa_lo + off, alo[mf][0], alo[mf][1], alo[mf][2], alo[mf][3]);
            }
#pragma unroll
            for (int p = 0; p < 2; p++) {
                int kr = ks + b_k;
                int n = wn * 32 + p * 16 + b_n;
                int off = boff(kr, n);
                ldm_x4t(sb_hi + off, bhi[2 * p][0], bhi[2 * p][1], bhi[2 * p + 1][0], bhi[2 * p + 1][1]);
                ldm_x4t(sb_lo + off, blo[2 * p][0], blo[2 * p][1], blo[2 * p + 1][0], blo[2 * p + 1][1]);
            }
#pragma unroll
            for (int mf = 0; mf < 2; mf++)
#pragma unroll
                for (int nf = 0; nf < 4; nf++) {
                    float* d = acc[mf][nf];
                    mma_bf16(d[0], d[1], d[2], d[3],
                             ahi[mf][0], ahi[mf][1], ahi[mf][2], ahi[mf][3],
                             bhi[nf][0], bhi[nf][1]);
                    mma_bf16(d[0], d[1], d[2], d[3],
                             ahi[mf][0], ahi[mf][1], ahi[mf][2], ahi[mf][3],
                             blo[nf][0], blo[nf][1]);
                    mma_bf16(d[0], d[1], d[2], d[3],
                             alo[mf][0], alo[mf][1], alo[mf][2], alo[mf][3],
                             bhi[nf][0], bhi[nf][1]);
                }
        }
        __syncthreads();
    }

    // epilogue
#pragma unroll
    for (int mf = 0; mf < 2; mf++) {
        int row0 = bm + wm * 32 + mf * 16 + (lane >> 2);
#pragma unroll
        for (int nf = 0; nf < 4; nf++) {
            int col = bn + wn * 32 + nf * 8 + (lane & 3) * 2;
            float b0 = bias ? bias[col] : 0.f;
            float b1 = bias ? bias[col + 1] : 0.f;
            float* d = acc[mf][nf];
            float c0 = d[0] + b0, c1 = d[1] + b1, c2 = d[2] + b0, c3 = d[3] + b1;
            if (actFlag) { c0 = tanhf(c0); c1 = tanhf(c1); c2 = tanhf(c2); c3 = tanhf(c3); }
            if (row0 < M) *(float2*)(C + (size_t)row0 * Nc + col) = make_float2(c0, c1);
            if (row0 + 8 < M) *(float2*)(C + (size_t)(row0 + 8) * Nc + col) = make_float2(c2, c3);
        }
    }
}

// ---------------- host orchestration ----------------
static inline void gemm2(const bf16* A1h, const bf16* A1l, int K1, const bf16* B1h, const bf16* B1l,
                         const bf16* A2h, const bf16* A2l, int K2, const bf16* B2h, const bf16* B2l,
                         float* C, int M, int Nc, const float* bias, int actFlag) {
    dim3 grid(Nc / 64, (M + 127) / 128);
    k_gemm_tc<<<grid, 256>>>(A1h, A1l, K1, B1h, B1l, A2h, A2l, K2, B2h, B2l,
                             C, M, Nc, bias, actFlag);
}
static inline void gemm1(const bf16* Ah, const bf16* Al, int K, const bf16* Bh, const bf16* Bl,
                         float* C, int M, int Nc, const float* bias, int actFlag) {
    gemm2(Ah, Al, K, Bh, Bl, nullptr, nullptr, 0, nullptr, nullptr, C, M, Nc, bias, actFlag);
}

extern "C" void kernel_launch(void* const* d_in, const int* in_sizes, int n_in,
                              void* d_out, int out_size) {
    (void)in_sizes; (void)n_in; (void)out_size;
    const float* x      = (const float*)d_in[0];
    const int*   A_idx  = (const int*)d_in[1];
    const float* A_val  = (const float*)d_in[2];
    const int*   L_idx  = (const int*)d_in[3];
    const float* L_val  = (const float*)d_in[4];
    const float* gcn_w0 = (const float*)d_in[5];
    const float* gcn_b0 = (const float*)d_in[6];
    const float* pai1_0 = (const float*)d_in[7];
    const float* pai2_0 = (const float*)d_in[8];
    const float* w1_w0  = (const float*)d_in[9];
    const float* w1_b0  = (const float*)d_in[10];
    const float* w2_w0  = (const float*)d_in[11];
    const float* w2_b0  = (const float*)d_in[12];
    const float* gcn_w1 = (const float*)d_in[13];
    const float* gcn_b1 = (const float*)d_in[14];
    const float* pai1_1 = (const float*)d_in[15];
    const float* pai2_1 = (const float*)d_in[16];
    const float* w1_w1  = (const float*)d_in[17];
    const float* w1_b1  = (const float*)d_in[18];
    const float* w2_w1  = (const float*)d_in[19];
    const float* w2_b1  = (const float*)d_in[20];

    float* out = (float*)d_out;
    float* out_ztp0 = out;
    float* out_ztp1 = out + (size_t)NNODES * FOUT;
    float* out_zem0 = out + (size_t)2 * NNODES * FOUT;
    float* out_zem1 = out + (size_t)3 * NNODES * FOUT;

    float *buf0, *buf1, *buf2, *buf3, *valA, *valL;
    bf16 *xhi, *xlo, *zhi, *zlo, *whi, *wlo;
    int *rowptrA, *colA, *rowptrL, *colL, *cnt, *cur, *part, *partex;
    cudaGetSymbolAddress((void**)&buf0, g_buf0);
    cudaGetSymbolAddress((void**)&buf1, g_buf1);
    cudaGetSymbolAddress((void**)&buf2, g_buf2);
    cudaGetSymbolAddress((void**)&buf3, g_buf3);
    cudaGetSymbolAddress((void**)&xhi, g_xhi);
    cudaGetSymbolAddress((void**)&xlo, g_xlo);
    cudaGetSymbolAddress((void**)&zhi, g_zhi);
    cudaGetSymbolAddress((void**)&zlo, g_zlo);
    cudaGetSymbolAddress((void**)&whi, g_whi);
    cudaGetSymbolAddress((void**)&wlo, g_wlo);
    cudaGetSymbolAddress((void**)&rowptrA, g_rowptrA);
    cudaGetSymbolAddress((void**)&colA, g_colA);
    cudaGetSymbolAddress((void**)&valA, g_valA);
    cudaGetSymbolAddress((void**)&rowptrL, g_rowptrL);
    cudaGetSymbolAddress((void**)&colL, g_colL);
    cudaGetSymbolAddress((void**)&valL, g_valL);
    cudaGetSymbolAddress((void**)&cnt, g_cnt);
    cudaGetSymbolAddress((void**)&cur, g_cur);
    cudaGetSymbolAddress((void**)&part, g_part);
    cudaGetSymbolAddress((void**)&partex, g_partex);

    const int TB = 256;
    int gbN = (NNODES + TB - 1) / TB;
    int gbE = (NEDGES + TB - 1) / TB;
    int nChunks = (NNODES + 1023) / 1024;

    // ---- build CSR for A ----
    k_zero_int<<<gbN, TB>>>(cnt, NNODES);
    k_zero_int<<<gbN, TB>>>(cur, NNODES);
    k_count<<<gbE, TB>>>(A_idx, cnt, NEDGES);
    k_scan_reduce<<<nChunks, 256>>>(cnt, part, NNODES);
    k_scan_part<<<1, 128>>>(part, partex, nChunks);
    k_scan_final<<<nChunks, 256>>>(cnt, partex, rowptrA, NNODES);
    k_scatter<<<gbE, TB>>>(A_idx, A_idx + NEDGES, A_val, rowptrA, cur, colA, valA, NEDGES);
    // ---- build CSR for L ----
    k_zero_int<<<gbN, TB>>>(cnt, NNODES);
    k_zero_int<<<gbN, TB>>>(cur, NNODES);
    k_count<<<gbE, TB>>>(L_idx, cnt, NEDGES);
    k_scan_reduce<<<nChunks, 256>>>(cnt, part, NNODES);
    k_scan_part<<<1, 128>>>(part, partex, nChunks);
    k_scan_final<<<nChunks, 256>>>(cnt, partex, rowptrL, NNODES);
    k_scatter<<<gbE, TB>>>(L_idx, L_idx + NEDGES, L_val, rowptrL, cur, colL, valL, NEDGES);

    // ---- split x and weights ----
    {
        int n4 = NNODES * FDIN / 4;
        k_split<<<(n4 + TB - 1) / TB, TB>>>(x, xhi, xlo, n4);
        WSplit ws;
        ws.src[0] = gcn_w0; ws.n4[0] = 65536 / 4; ws.off[0] = OFF_GCN_W0;
        ws.src[1] = pai1_0; ws.n4[1] = 65536 / 4; ws.off[1] = OFF_PAI1_0;
        ws.src[2] = pai2_0; ws.n4[2] = 65536 / 4; ws.off[2] = OFF_PAI2_0;
        ws.src[3] = w1_w0;  ws.n4[3] = 16384 / 4; ws.off[3] = OFF_W1_W0;
        ws.src[4] = w2_w0;  ws.n4[4] = 16384 / 4; ws.off[4] = OFF_W2_W0;
        ws.src[5] = gcn_w1; ws.n4[5] = 16384 / 4; ws.off[5] = OFF_GCN_W1;
        ws.src[6] = pai1_1; ws.n4[6] = 4096 / 4;  ws.off[6] = OFF_PAI1_1;
        ws.src[7] = pai2_1; ws.n4[7] = 16384 / 4; ws.off[7] = OFF_PAI2_1;
        ws.src[8] = w1_w1;  ws.n4[8] = 4096 / 4;  ws.off[8] = OFF_W1_W1;
        ws.src[9] = w2_w1;  ws.n4[9] = 4096 / 4;  ws.off[9] = OFF_W2_W1;
        dim3 grid(64, 10);
        k_split_weights<<<grid, TB>>>(ws, whi, wlo);
    }

    // ================= layer 0 (din=256 -> h=256) =================
    gemm1(xhi, xlo, FDIN, whi + OFF_GCN_W0, wlo + OFF_GCN_W0, buf0, NNODES, FH, nullptr, 0);
    {
        int threads = NNODES * (FH / 4);
        k_spmm_relu<FH / 4><<<(threads + TB - 1) / TB, TB>>>(rowptrA, colA, valA, buf0, gcn_b0, buf1);
    }
    {
        int n4 = NNODES * FH / 4;
        k_split<<<(n4 + TB - 1) / TB, TB>>>(buf1, zhi, zlo, n4);
    }
    gemm1(zhi, zlo, FH, whi + OFF_W1_W0, wlo + OFF_W1_W0, out_ztp0, NNODES, FOUT, w1_b0, 1);
    gemm2(zhi, zlo, FH, whi + OFF_PAI1_0, wlo + OFF_PAI1_0,
          xhi, xlo, FDIN, whi + OFF_PAI2_0, wlo + OFF_PAI2_0,
          buf2, NNODES, FH, nullptr, 0);
    {
        int threads = NNODES * (FH / 4);
        k_spmm_embed<FH / 4><<<(threads + TB - 1) / TB, TB>>>(rowptrL, colL, valL, buf1, buf2, buf3);
    }
    {
        int n4 = NNODES * FH / 4;
        k_split<<<(n4 + TB - 1) / TB, TB>>>(buf3, zhi, zlo, n4);
    }
    gemm1(zhi, zlo, FH, whi + OFF_W2_W0, wlo + OFF_W2_W0, out_zem0, NNODES, FOUT, w2_b0, 1);

    // ================= layer 1 (h=256 -> dout=64) =================
    gemm1(zhi, zlo, FH, whi + OFF_GCN_W1, wlo + OFF_GCN_W1, buf0, NNODES, FOUT, nullptr, 0);
    {
        int threads = NNODES * (FOUT / 4);
        k_spmm_relu<FOUT / 4><<<(threads + TB - 1) / TB, TB>>>(rowptrA, colA, valA, buf0, gcn_b1, buf1);
    }
    {
        int n4 = NNODES * FOUT / 4;
        k_split<<<(n4 + TB - 1) / TB, TB>>>(buf1, zhi, zlo, n4);
    }
    gemm1(zhi, zlo, FOUT, whi + OFF_W1_W1, wlo + OFF_W1_W1, out_ztp1, NNODES, FOUT, w1_b1, 1);
    gemm2(zhi, zlo, FOUT, whi + OFF_PAI1_1, wlo + OFF_PAI1_1,
          xhi, xlo, FDIN, whi + OFF_PAI2_1, wlo + OFF_PAI2_1,
          buf2, NNODES, FOUT, nullptr, 0);
    {
        int threads = NNODES * (FOUT / 4);
        k_spmm_embed<FOUT / 4><<<(threads + TB - 1) / TB, TB>>>(rowptrL, colL, valL, buf1, buf2, buf3);
    }
    {
        int n4 = NNODES * FOUT / 4;
        k_split<<<(n4 + TB - 1) / TB, TB>>>(buf3, zhi, zlo, n4);
    }
    gemm1(zhi, zlo, FOUT, whi + OFF_W2_W1, wlo + OFF_W2_W1, out_zem1, NNODES, FOUT, w2_b1, 1);
}